// round 7
// baseline (speedup 1.0000x reference)
#include <cuda_runtime.h>
#include <cuda_bf16.h>
#include <math.h>
#include <stdint.h>

#define BB 2
#define SS 2048
#define DD 1024
#define NH 16
#define NKV 4
#define HD 64
#define GATE_CH 12
#define EPSV 1e-6f
#define QKVLD 1536   // qkv buffer row stride: [q(1024) | k(256) | v(256)]

// Scratch (allocation-free rule: __device__ globals)
__device__ float g_qkv[BB * SS * QKVLD];     // [b*s][1536]
__device__ float g_y[BB * SS * DD];          // attention output [b*s][1024]
// packed bf16 hi/lo (u32 = odd<<16 | even), 64 u32 per head-vector:
// [0..31] = hi pairs, [32..63] = lo pairs
__device__ uint32_t g_qpk[BB * SS * NH * 64];
__device__ uint32_t g_kpk[BB * SS * NKV * 64];

__device__ __forceinline__ float to_tf32(float x) {
    float r;
    asm("cvt.rna.tf32.f32 %0, %1;" : "=f"(r) : "f"(x));
    return r;
}
__device__ __forceinline__ uint32_t pack_bf16(float e, float o) {
    uint16_t a = __bfloat16_as_ushort(__float2bfloat16(e));
    uint16_t b = __bfloat16_as_ushort(__float2bfloat16(o));
    return ((uint32_t)b << 16) | a;
}

__device__ __forceinline__ void mma_tf32(float* d, const uint32_t* a, const uint32_t* b) {
    asm volatile(
        "mma.sync.aligned.m16n8k8.row.col.f32.tf32.tf32.f32 "
        "{%0,%1,%2,%3}, {%4,%5,%6,%7}, {%8,%9}, {%0,%1,%2,%3};\n"
        : "+f"(d[0]), "+f"(d[1]), "+f"(d[2]), "+f"(d[3])
        : "r"(a[0]), "r"(a[1]), "r"(a[2]), "r"(a[3]), "r"(b[0]), "r"(b[1]));
}
__device__ __forceinline__ void mma_bf16(float* d, const uint32_t* a, const uint32_t* b) {
    asm volatile(
        "mma.sync.aligned.m16n8k16.row.col.f32.bf16.bf16.f32 "
        "{%0,%1,%2,%3}, {%4,%5,%6,%7}, {%8,%9}, {%0,%1,%2,%3};\n"
        : "+f"(d[0]), "+f"(d[1]), "+f"(d[2]), "+f"(d[3])
        : "r"(a[0]), "r"(a[1]), "r"(a[2]), "r"(a[3]), "r"(b[0]), "r"(b[1]));
}

__device__ __forceinline__ void cp_async16(uint32_t saddr, const void* gptr) {
    asm volatile("cp.async.cg.shared.global [%0], [%1], 16;" :: "r"(saddr), "l"(gptr));
}
#define CP_COMMIT() asm volatile("cp.async.commit_group;")
#define CP_WAIT(n)  asm volatile("cp.async.wait_group %0;" :: "n"(n))

// ---------------------------------------------------------------------------
// tf32 tensor-core GEMM, 2-stage pipelined (unchanged)
// ---------------------------------------------------------------------------
template<int QKV>
__global__ __launch_bounds__(256, 2) void gemm_tf32(
    const float* __restrict__ A,
    const float* __restrict__ W0, const float* __restrict__ W1,
    const float* __restrict__ W2,
    float* __restrict__ C, int K, int ldc)
{
    __shared__ float As[2][128][20];
    __shared__ float Bs[2][16][136];

    const int tid = threadIdx.x;
    const int lane = tid & 31;
    const int wid = tid >> 5;
    const int gid = lane >> 2;
    const int tig = lane & 3;
    const int warp_m = (wid >> 2) * 64;
    const int warp_n = (wid & 3) * 32;
    const int rowBase = blockIdx.y * 128;
    const int colBase = blockIdx.x * 128;

    const float* W;
    int ldw, wcol;
    if (QKV) {
        if (colBase < 1024)      { W = W0; ldw = 1024; wcol = colBase; }
        else if (colBase < 1280) { W = W1; ldw = 256;  wcol = colBase - 1024; }
        else                     { W = W2; ldw = 256;  wcol = colBase - 1280; }
    } else { W = W0; ldw = ldc; wcol = colBase; }

    const int a_r0 = tid >> 2;            const int a_c0 = (tid & 3) * 4;
    const int a_r1 = (tid + 256) >> 2;    const int a_c1 = a_c0;
    const int b_r0 = tid >> 5;            const int b_c0 = (tid & 31) * 4;
    const int b_r1 = (tid + 256) >> 5;    const int b_c1 = b_c0;

    const float* Abase0 = A + (size_t)(rowBase + a_r0) * K + a_c0;
    const float* Abase1 = A + (size_t)(rowBase + a_r1) * K + a_c1;
    const float* Wbase0 = W + (size_t)b_r0 * ldw + wcol + b_c0;
    const float* Wbase1 = W + (size_t)b_r1 * ldw + wcol + b_c1;

    float acc[4][4][4] = {};
    float4 ra0, ra1, rb0, rb1;

    ra0 = *(const float4*)Abase0;
    ra1 = *(const float4*)Abase1;
    rb0 = *(const float4*)Wbase0;
    rb1 = *(const float4*)Wbase1;
    {
        float4 t;
        t = ra0; t.x=to_tf32(t.x); t.y=to_tf32(t.y); t.z=to_tf32(t.z); t.w=to_tf32(t.w);
        *(float4*)&As[0][a_r0][a_c0] = t;
        t = ra1; t.x=to_tf32(t.x); t.y=to_tf32(t.y); t.z=to_tf32(t.z); t.w=to_tf32(t.w);
        *(float4*)&As[0][a_r1][a_c1] = t;
        t = rb0; t.x=to_tf32(t.x); t.y=to_tf32(t.y); t.z=to_tf32(t.z); t.w=to_tf32(t.w);
        *(float4*)&Bs[0][b_r0][b_c0] = t;
        t = rb1; t.x=to_tf32(t.x); t.y=to_tf32(t.y); t.z=to_tf32(t.z); t.w=to_tf32(t.w);
        *(float4*)&Bs[0][b_r1][b_c1] = t;
    }
    __syncthreads();

    const int iters = K / 16;
    for (int it = 0; it < iters; it++) {
        const int s = it & 1;
        const bool more = (it + 1) < iters;
        if (more) {
            int k0n = (it + 1) * 16;
            ra0 = *(const float4*)(Abase0 + k0n);
            ra1 = *(const float4*)(Abase1 + k0n);
            rb0 = *(const float4*)(Wbase0 + (size_t)k0n * ldw);
            rb1 = *(const float4*)(Wbase1 + (size_t)k0n * ldw);
        }

#pragma unroll
        for (int ks = 0; ks < 16; ks += 8) {
            uint32_t af[4][4], bf[4][2];
#pragma unroll
            for (int mi = 0; mi < 4; mi++) {
                int r0 = warp_m + mi * 16 + gid;
                af[mi][0] = __float_as_uint(As[s][r0][ks + tig]);
                af[mi][1] = __float_as_uint(As[s][r0 + 8][ks + tig]);
                af[mi][2] = __float_as_uint(As[s][r0][ks + tig + 4]);
                af[mi][3] = __float_as_uint(As[s][r0 + 8][ks + tig + 4]);
            }
#pragma unroll
            for (int ni = 0; ni < 4; ni++) {
                int c0 = warp_n + ni * 8 + gid;
                bf[ni][0] = __float_as_uint(Bs[s][ks + tig][c0]);
                bf[ni][1] = __float_as_uint(Bs[s][ks + tig + 4][c0]);
            }
#pragma unroll
            for (int mi = 0; mi < 4; mi++)
#pragma unroll
                for (int ni = 0; ni < 4; ni++)
                    mma_tf32(acc[mi][ni], af[mi], bf[ni]);
        }

        if (more) {
            const int d = s ^ 1;
            float4 t;
            t = ra0; t.x=to_tf32(t.x); t.y=to_tf32(t.y); t.z=to_tf32(t.z); t.w=to_tf32(t.w);
            *(float4*)&As[d][a_r0][a_c0] = t;
            t = ra1; t.x=to_tf32(t.x); t.y=to_tf32(t.y); t.z=to_tf32(t.z); t.w=to_tf32(t.w);
            *(float4*)&As[d][a_r1][a_c1] = t;
            t = rb0; t.x=to_tf32(t.x); t.y=to_tf32(t.y); t.z=to_tf32(t.z); t.w=to_tf32(t.w);
            *(float4*)&Bs[d][b_r0][b_c0] = t;
            t = rb1; t.x=to_tf32(t.x); t.y=to_tf32(t.y); t.z=to_tf32(t.z); t.w=to_tf32(t.w);
            *(float4*)&Bs[d][b_r1][b_c1] = t;
        }
        __syncthreads();
    }

#pragma unroll
    for (int mi = 0; mi < 4; mi++) {
#pragma unroll
        for (int ni = 0; ni < 4; ni++) {
            int row = rowBase + warp_m + mi * 16 + gid;
            int col = colBase + warp_n + ni * 8 + 2 * tig;
            *(float2*)(C + (size_t)row * ldc + col) =
                make_float2(acc[mi][ni][0], acc[mi][ni][1]);
            *(float2*)(C + (size_t)(row + 8) * ldc + col) =
                make_float2(acc[mi][ni][2], acc[mi][ni][3]);
        }
    }
}

// ---------------------------------------------------------------------------
// Fused prep: hh in [0,20) -> RoPE+RMSNorm for q/k (emit packed bf16 hi/lo);
//             hh in [20,24) -> v gate (+ tf32 round in place).
// grid = B*S*24, block = 64
// ---------------------------------------------------------------------------
__global__ void prep_kernel(const float* __restrict__ cosp,
                            const float* __restrict__ sinp,
                            const float* __restrict__ x,
                            const float* __restrict__ ve,
                            const float* __restrict__ Wg)
{
    int blk = blockIdx.x;
    int hh = blk % (NH + NKV + NKV);
    int bs = blk / (NH + NKV + NKV);
    int d = threadIdx.x;

    if (hh >= NH + NKV) {
        // ---- v gate ----
        int kvh = hh - (NH + NKV);
        const float* xr = x + (size_t)bs * DD;
        float g = 0.f;
#pragma unroll
        for (int c = 0; c < GATE_CH; c++) g += xr[c] * Wg[c * NKV + kvh];
        g = 3.f / (1.f + __expf(-g));
        float* vp = &g_qkv[(size_t)bs * QKVLD + 1280 + kvh * HD + d];
        *vp = to_tf32(*vp + g * ve[(size_t)bs * (NKV * HD) + kvh * HD + d]);
        return;
    }

    // ---- RoPE + RMSNorm ----
    int s = bs % SS;
    const float* ptr = g_qkv + (size_t)bs * QKVLD +
                       ((hh < NH) ? hh * HD : 1024 + (hh - NH) * HD);

    int half = d & 31;
    float c  = cosp[s * 32 + half];
    float sn = sinp[s * 32 + half];
    float x1 = ptr[half];
    float x2 = ptr[half + 32];
    float rot = (d < 32) ? (x1 * c + x2 * sn) : (-x1 * sn + x2 * c);

    __shared__ float red[2];
    float v = rot * rot;
#pragma unroll
    for (int o = 16; o > 0; o >>= 1) v += __shfl_xor_sync(0xffffffffu, v, o);
    if ((d & 31) == 0) red[d >> 5] = v;
    __syncthreads();
    float total = red[0] + red[1];
    float r = rsqrtf(total * (1.f / HD) + EPSV) * 1.2f;
    float val = rot * r;
    if (hh < NH) val *= 0.125f;   // fold 1/sqrt(hd) into q

    float hif = __bfloat162float(__float2bfloat16(val));
    float lof = val - hif;
    float val_o = __shfl_down_sync(0xffffffffu, val, 1);
    float lof_o = __shfl_down_sync(0xffffffffu, lof, 1);

    if ((d & 1) == 0) {
        uint32_t hp = pack_bf16(val, val_o);
        uint32_t lp = pack_bf16(lof, lof_o);
        uint32_t* out = (hh < NH)
            ? &g_qpk[((size_t)bs * NH + hh) * 64]
            : &g_kpk[((size_t)bs * NKV + (hh - NH)) * 64];
        out[d >> 1]        = hp;
        out[32 + (d >> 1)] = lp;
    }
}

// ---------------------------------------------------------------------------
// Tensor-core flash attention, 128 queries/CTA, 8 warps.
// QK^T: bf16 m16n8k16 hi/lo compensated; PV: tf32 m16n8k8.
// grid = B*NH*(S/128), block = 256.
// smem f32 units: Khl[2][64][68](u32) | Vb[2][64][68] | Ss[128][68] | scb[128] | lbuf[128]
// ---------------------------------------------------------------------------
#define ATS 68
#define TILEF (64 * ATS)
__global__ __launch_bounds__(256, 2) void attn_tc(const int* __restrict__ winp)
{
    const int win = *winp;
    int bid = blockIdx.x;
    int qt = bid & 15;
    int bh = bid >> 4;
    int h = bh % NH;
    int b = bh / NH;
    int q0 = qt * 128;
    int kvh = h / (NH / NKV);

    const int tid = threadIdx.x;
    const int lane = tid & 31;
    const int warp = tid >> 5;        // 0..7
    const int wrow = warp * 16;       // 0..112
    const int gid = lane >> 2;
    const int tig = lane & 3;

    extern __shared__ float sm[];
    uint32_t* Khl0 = (uint32_t*)sm;           // 2 buffers packed K
    float* Ss   = sm + 4 * TILEF;             // 128 x ATS
    float* scb  = sm + 4 * TILEF + 128 * ATS; // 128
    float* lbuf = scb + 128;                  // 128
    uint32_t smbase = (uint32_t)__cvta_generic_to_shared(sm);

    // staging coords: 256 threads cover 64 rows x 64 u32 in 4 steps of 16 rows
    const int st_r  = tid >> 4;          // 0..15 (+16 per step)
    const int st_c4 = (tid & 15) * 4;    // 0..60

    // ---- stage packed Q tile (128 rows) into Ss region, build fragments ----
    {
        uint32_t* Qs = (uint32_t*)Ss;
        for (int i = tid; i < 128 * 16; i += 256) {
            int r = i >> 4;
            int c4 = (i & 15) * 4;
            *(uint4*)&Qs[r * ATS + c4] =
                *(const uint4*)(g_qpk + ((size_t)(b * SS + q0 + r) * NH + h) * 64 + c4);
        }
    }
    __syncthreads();

    uint32_t ahi[4][4], alo[4][4];
    {
        const uint32_t* Qs = (const uint32_t*)Ss;
#pragma unroll
        for (int ks = 0; ks < 4; ks++) {
            int cb = ks * 8 + tig;
            ahi[ks][0] = Qs[(wrow + gid) * ATS + cb];
            ahi[ks][1] = Qs[(wrow + gid + 8) * ATS + cb];
            ahi[ks][2] = Qs[(wrow + gid) * ATS + cb + 4];
            ahi[ks][3] = Qs[(wrow + gid + 8) * ATS + cb + 4];
            alo[ks][0] = Qs[(wrow + gid) * ATS + 32 + cb];
            alo[ks][1] = Qs[(wrow + gid + 8) * ATS + 32 + cb];
            alo[ks][2] = Qs[(wrow + gid) * ATS + 32 + cb + 4];
            alo[ks][3] = Qs[(wrow + gid + 8) * ATS + 32 + cb + 4];
        }
    }

    float m = -1e30f, lsum = 0.f;
    float oacc[8][4] = {};

    int kmin = q0 - win + 1;
    if (kmin < 0) kmin = 0;
    int t0 = kmin >> 6;
    int t1 = (q0 + 127) >> 6;

    // ---- prologue: async-stage tile t0 into buffer 0 ----
    {
        int kb = t0 << 6;
        const uint32_t* ksrc = g_kpk + ((size_t)(b * SS + kb + st_r) * NKV + kvh) * 64 + st_c4;
        const float* vsrc = g_qkv + (size_t)(b * SS + kb + st_r) * QKVLD + 1280 + kvh * HD + st_c4;
        uint32_t kdst = smbase + (0 * TILEF + st_r * ATS + st_c4) * 4;
        uint32_t vdst = smbase + (2 * TILEF + st_r * ATS + st_c4) * 4;
#pragma unroll
        for (int j = 0; j < 4; j++) {
            cp_async16(kdst + j * 16 * ATS * 4, ksrc + (size_t)j * 16 * NKV * 64);
            cp_async16(vdst + j * 16 * ATS * 4, vsrc + (size_t)j * 16 * QKVLD);
        }
        CP_COMMIT();
    }

    for (int t = t0; t <= t1; t++) {
        int kb = t << 6;
        const int buf = (t - t0) & 1;
        __syncthreads();   // everyone done reading buf^1 from iter t-1
        if (t < t1) {
            int nb = (t + 1) << 6;
            const uint32_t* ksrc = g_kpk + ((size_t)(b * SS + nb + st_r) * NKV + kvh) * 64 + st_c4;
            const float* vsrc = g_qkv + (size_t)(b * SS + nb + st_r) * QKVLD + 1280 + kvh * HD + st_c4;
            uint32_t kdst = smbase + ((buf ^ 1) * TILEF + st_r * ATS + st_c4) * 4;
            uint32_t vdst = smbase + ((2 + (buf ^ 1)) * TILEF + st_r * ATS + st_c4) * 4;
#pragma unroll
            for (int j = 0; j < 4; j++) {
                cp_async16(kdst + j * 16 * ATS * 4, ksrc + (size_t)j * 16 * NKV * 64);
                cp_async16(vdst + j * 16 * ATS * 4, vsrc + (size_t)j * 16 * QKVLD);
            }
            CP_COMMIT();
            CP_WAIT(1);
        } else {
            CP_WAIT(0);
        }
        __syncthreads();

        // per-warp tile skip: does this 64-key tile touch my 16 query rows?
        bool active = (kb <= q0 + wrow + 15) && (kb + 63 >= q0 + wrow - win + 1);
        if (active) {
            const uint32_t* Khl = Khl0 + buf * TILEF;
            const float* Vs = sm + (2 + buf) * TILEF;

            // ---- S = Q @ K^T : bf16 hi/lo ----
            float accS[8][4] = {};
#pragma unroll
            for (int ks = 0; ks < 4; ks++) {
#pragma unroll
                for (int ni = 0; ni < 8; ni++) {
                    const uint32_t* kr = &Khl[(ni * 8 + gid) * ATS + ks * 8 + tig];
                    uint32_t bh2[2] = { kr[0],  kr[4] };
                    uint32_t bl2[2] = { kr[32], kr[36] };
                    mma_bf16(accS[ni], ahi[ks], bh2);
                    mma_bf16(accS[ni], alo[ks], bh2);
                    mma_bf16(accS[ni], ahi[ks], bl2);
                }
            }

            // ---- write masked S to smem (warp-private rows) ----
#pragma unroll
            for (int ni = 0; ni < 8; ni++) {
#pragma unroll
                for (int j = 0; j < 4; j++) {
                    int col = ni * 8 + 2 * tig + (j & 1);
                    int r = gid + ((j >> 1) << 3);
                    int qpos = q0 + wrow + r;
                    int kpos = kb + col;
                    bool ok = (kpos <= qpos) && (kpos >= qpos - win + 1);
                    Ss[(wrow + r) * ATS + col] = ok ? accS[ni][j] : -1e30f;
                }
            }
            __syncwarp();

            // ---- online softmax: 2 lanes per row, 32 cols each ----
            {
                int srow = lane >> 1;
                int cb = (lane & 1) * 32;
                float* sp = &Ss[(wrow + srow) * ATS + cb];
                float rmax = -1e30f;
#pragma unroll
                for (int c = 0; c < 32; c++) rmax = fmaxf(rmax, sp[c]);
                rmax = fmaxf(rmax, __shfl_xor_sync(0xffffffffu, rmax, 1));
                float mnew = fmaxf(m, rmax);
                float scale, rs = 0.f;
                if (mnew <= -1e20f) {
                    scale = 1.f;
#pragma unroll
                    for (int c = 0; c < 32; c++) sp[c] = 0.f;
                } else {
                    scale = __expf(m - mnew);
#pragma unroll
                    for (int c = 0; c < 32; c++) {
                        float p = __expf(sp[c] - mnew);
                        rs += p;
                        sp[c] = to_tf32(p);
                    }
                }
                m = mnew;
                rs += __shfl_xor_sync(0xffffffffu, rs, 1);
                lsum = lsum * scale + rs;
                if ((lane & 1) == 0) scb[wrow + srow] = scale;
            }
            __syncwarp();

            // ---- rescale O, then O += P @ V (tf32) ----
            {
                float sc0 = scb[wrow + gid];
                float sc1 = scb[wrow + gid + 8];
#pragma unroll
                for (int ni = 0; ni < 8; ni++) {
                    oacc[ni][0] *= sc0; oacc[ni][1] *= sc0;
                    oacc[ni][2] *= sc1; oacc[ni][3] *= sc1;
                }
            }
#pragma unroll
            for (int ks = 0; ks < 8; ks++) {
                uint32_t pa[4];
                pa[0] = __float_as_uint(Ss[(wrow + gid) * ATS + ks * 8 + tig]);
                pa[1] = __float_as_uint(Ss[(wrow + gid + 8) * ATS + ks * 8 + tig]);
                pa[2] = __float_as_uint(Ss[(wrow + gid) * ATS + ks * 8 + tig + 4]);
                pa[3] = __float_as_uint(Ss[(wrow + gid + 8) * ATS + ks * 8 + tig + 4]);
#pragma unroll
                for (int ni = 0; ni < 8; ni++) {
                    uint32_t vb[2];
                    vb[0] = __float_as_uint(Vs[(ks * 8 + tig) * ATS + ni * 8 + gid]);
                    vb[1] = __float_as_uint(Vs[(ks * 8 + tig + 4) * ATS + ni * 8 + gid]);
                    mma_tf32(oacc[ni], pa, vb);
                }
            }
        }
    }

    // ---- normalize and write out ----
    if ((lane & 1) == 0) lbuf[wrow + (lane >> 1)] = lsum;
    __syncwarp();
    float li0 = 1.f / lbuf[wrow + gid];
    float li1 = 1.f / lbuf[wrow + gid + 8];

#pragma unroll
    for (int ni = 0; ni < 8; ni++) {
        int col = h * HD + ni * 8 + 2 * tig;
        int row0 = b * SS + q0 + wrow + gid;
        *(float2*)(g_y + (size_t)row0 * DD + col) =
            make_float2(oacc[ni][0] * li0, oacc[ni][1] * li0);
        *(float2*)(g_y + (size_t)(row0 + 8) * DD + col) =
            make_float2(oacc[ni][2] * li1, oacc[ni][3] * li1);
    }
}

// ---------------------------------------------------------------------------
extern "C" void kernel_launch(void* const* d_in, const int* in_sizes, int n_in,
                              void* d_out, int out_size)
{
    const float* x    = (const float*)d_in[0];
    const float* ve   = (const float*)d_in[1];
    const float* cosp = (const float*)d_in[2];
    const float* sinp = (const float*)d_in[3];
    const float* Wq   = (const float*)d_in[4];
    const float* Wk   = (const float*)d_in[5];
    const float* Wv   = (const float*)d_in[6];
    const float* Wo   = (const float*)d_in[7];
    const float* Wg   = (const float*)d_in[8];
    const int*   win  = (const int*)d_in[9];
    float* out = (float*)d_out;

    float *pqkv, *py;
    cudaGetSymbolAddress((void**)&pqkv, g_qkv);
    cudaGetSymbolAddress((void**)&py, g_y);

    const int M = BB * SS;   // 4096

    // Fused QKV projection (tf32 tensor cores, pipelined)
    {
        dim3 g(QKVLD / 128, M / 128);
        gemm_tf32<1><<<g, 256>>>(x, Wq, Wk, Wv, pqkv, DD, QKVLD);
    }

    // Fused v-gate + RoPE/RMSNorm + bf16 hi/lo packing
    prep_kernel<<<M * (NH + 2 * NKV), HD>>>(cosp, sinp, x, ve, Wg);

    // Tensor-core flash attention (128 queries/CTA, 8 warps)
    {
        int smem = (4 * TILEF + 128 * ATS + 256) * sizeof(float);   // 105472 B
        cudaFuncSetAttribute(attn_tc, cudaFuncAttributeMaxDynamicSharedMemorySize, smem);
        attn_tc<<<BB * NH * (SS / 128), 256, smem>>>(win);
    }

    // Output projection (tf32 tensor cores, pipelined)
    {
        dim3 g(DD / 128, M / 128);
        gemm_tf32<0><<<g, 256>>>(py, Wo, nullptr, nullptr, out, DD, DD);
    }
}

// round 9
// speedup vs baseline: 1.0147x; 1.0147x over previous
#include <cuda_runtime.h>
#include <cuda_bf16.h>
#include <math.h>
#include <stdint.h>

#define BB 2
#define SS 2048
#define DD 1024
#define NH 16
#define NKV 4
#define HD 64
#define GATE_CH 12
#define EPSV 1e-6f
#define QKVLD 1536   // qkv buffer row stride: [q(1024) | k(256) | v(256)]

// ---------------- device scratch (allocation-free rule) ----------------
__device__ float    g_qkv[BB * SS * QKVLD];     // fp32 qkv
__device__ float    g_y[BB * SS * DD];          // attention output (tf32-rounded)
__device__ float    g_xr[BB * SS * DD];         // x rounded to tf32
__device__ float    g_wqkv[DD * QKVLD];         // [k][1536] = Wq|Wk|Wv, tf32
__device__ float    g_wo[DD * DD];              // Wo, tf32
__device__ uint32_t g_qpk[BB * SS * NH * 64];   // q packed bf16 hi|lo
__device__ uint32_t g_kpk[BB * SS * NKV * 64];  // k packed bf16 hi|lo

// ---------------- helpers ----------------
__device__ __forceinline__ float to_tf32(float x) {
    float r; asm("cvt.rna.tf32.f32 %0, %1;" : "=f"(r) : "f"(x)); return r;
}
__device__ __forceinline__ uint32_t pack_bf16(float e, float o) {
    uint16_t a = __bfloat16_as_ushort(__float2bfloat16(e));
    uint16_t b = __bfloat16_as_ushort(__float2bfloat16(o));
    return ((uint32_t)b << 16) | a;
}
__device__ __forceinline__ void mma_tf32(float* d, const uint32_t* a, const uint32_t* b) {
    asm volatile(
        "mma.sync.aligned.m16n8k8.row.col.f32.tf32.tf32.f32 "
        "{%0,%1,%2,%3}, {%4,%5,%6,%7}, {%8,%9}, {%0,%1,%2,%3};\n"
        : "+f"(d[0]), "+f"(d[1]), "+f"(d[2]), "+f"(d[3])
        : "r"(a[0]), "r"(a[1]), "r"(a[2]), "r"(a[3]), "r"(b[0]), "r"(b[1]));
}
__device__ __forceinline__ void mma_bf16(float* d, const uint32_t* a, const uint32_t* b) {
    asm volatile(
        "mma.sync.aligned.m16n8k16.row.col.f32.bf16.bf16.f32 "
        "{%0,%1,%2,%3}, {%4,%5,%6,%7}, {%8,%9}, {%0,%1,%2,%3};\n"
        : "+f"(d[0]), "+f"(d[1]), "+f"(d[2]), "+f"(d[3])
        : "r"(a[0]), "r"(a[1]), "r"(a[2]), "r"(a[3]), "r"(b[0]), "r"(b[1]));
}
__device__ __forceinline__ void cp_async16(uint32_t saddr, const void* gptr) {
    asm volatile("cp.async.cg.shared.global [%0], [%1], 16;" :: "r"(saddr), "l"(gptr));
}
#define CP_COMMIT() asm volatile("cp.async.commit_group;")
#define CP_WAIT(n)  asm volatile("cp.async.wait_group %0;" :: "n"(n))

// ---------------------------------------------------------------------------
// tf32 rounding kernels (run once per launch; operands become raw-copyable)
// ---------------------------------------------------------------------------
__global__ void round_x(const float* __restrict__ x)
{
    int bs = blockIdx.x, t = threadIdx.x;
    float4 v = *(const float4*)(x + (size_t)bs * DD + t * 4);
    v.x = to_tf32(v.x); v.y = to_tf32(v.y); v.z = to_tf32(v.z); v.w = to_tf32(v.w);
    *(float4*)(g_xr + (size_t)bs * DD + t * 4) = v;
}
__global__ void round_w(const float* __restrict__ W, float* __restrict__ dst,
                        int ncols, int ldd, int colofs)
{
    size_t i = (size_t)blockIdx.x * blockDim.x + threadIdx.x;   // float4 index
    float4 v = ((const float4*)W)[i];
    v.x = to_tf32(v.x); v.y = to_tf32(v.y); v.z = to_tf32(v.z); v.w = to_tf32(v.w);
    size_t e = i * 4;
    int k = (int)(e / ncols), n = (int)(e % ncols);
    *(float4*)(dst + (size_t)k * ldd + colofs + n) = v;
}

// ---------------------------------------------------------------------------
// tf32 tensor-core GEMM, 3-stage cp.async pipeline. C[M,N] = A[M,K] @ W[K,N].
// Operands pre-rounded to tf32. CTA 128x128, BK=16, 256 thr, warp tile 64x32.
// dyn smem: 3 x (As[128][20] | Bs[16][136]) = 56832 B
// ---------------------------------------------------------------------------
#define AS_OFF(s) ((s) * 2560)
#define BS_OFF(s) (7680 + (s) * 2176)
#define GCA_SMEM 56832
__global__ __launch_bounds__(256, 2) void gemm_ca(
    const float* __restrict__ A, const float* __restrict__ W,
    float* __restrict__ C, int K, int ldw, int ldc)
{
    extern __shared__ float smg[];
    uint32_t smb = (uint32_t)__cvta_generic_to_shared(smg);

    const int tid = threadIdx.x;
    const int lane = tid & 31, wid = tid >> 5;
    const int gid = lane >> 2, tig = lane & 3;
    const int warp_m = (wid >> 2) * 64, warp_n = (wid & 3) * 32;
    const int rowBase = blockIdx.y * 128, colBase = blockIdx.x * 128;

    const int a_r0 = tid >> 2, a_c = (tid & 3) * 4;
    const int a_r1 = a_r0 + 64;
    const int b_r0 = tid >> 5, b_c = (tid & 31) * 4;
    const int b_r1 = b_r0 + 8;
    const float* pa0 = A + (size_t)(rowBase + a_r0) * K + a_c;
    const float* pa1 = A + (size_t)(rowBase + a_r1) * K + a_c;
    const float* pb0 = W + (size_t)b_r0 * ldw + colBase + b_c;
    const float* pb1 = W + (size_t)b_r1 * ldw + colBase + b_c;

#define GCA_STAGE(k0, s) do { \
    cp_async16(smb + (AS_OFF(s) + a_r0 * 20 + a_c) * 4, pa0 + (k0)); \
    cp_async16(smb + (AS_OFF(s) + a_r1 * 20 + a_c) * 4, pa1 + (k0)); \
    cp_async16(smb + (BS_OFF(s) + b_r0 * 136 + b_c) * 4, pb0 + (size_t)(k0) * ldw); \
    cp_async16(smb + (BS_OFF(s) + b_r1 * 136 + b_c) * 4, pb1 + (size_t)(k0) * ldw); \
    CP_COMMIT(); \
} while (0)

    GCA_STAGE(0, 0);
    GCA_STAGE(16, 1);

    float acc[4][4][4] = {};
    const int nc = K / 16;
    for (int it = 0; it < nc; it++) {
        const int s = it % 3;
        __syncthreads();                       // all warps done compute(it-1)
        if (it + 2 < nc) {
            GCA_STAGE((it + 2) * 16, (it + 2) % 3);
            CP_WAIT(2);
        } else if (it + 1 < nc) {
            CP_WAIT(1);
        } else {
            CP_WAIT(0);
        }
        __syncthreads();                       // staged data visible

        const float* As = smg + AS_OFF(s);
        const float* Bs = smg + BS_OFF(s);
#pragma unroll
        for (int ks = 0; ks < 16; ks += 8) {
            uint32_t af[4][4], bf[4][2];
#pragma unroll
            for (int mi = 0; mi < 4; mi++) {
                int r0 = warp_m + mi * 16 + gid;
                af[mi][0] = __float_as_uint(As[r0 * 20 + ks + tig]);
                af[mi][1] = __float_as_uint(As[(r0 + 8) * 20 + ks + tig]);
                af[mi][2] = __float_as_uint(As[r0 * 20 + ks + tig + 4]);
                af[mi][3] = __float_as_uint(As[(r0 + 8) * 20 + ks + tig + 4]);
            }
#pragma unroll
            for (int ni = 0; ni < 4; ni++) {
                int c0 = warp_n + ni * 8 + gid;
                bf[ni][0] = __float_as_uint(Bs[(ks + tig) * 136 + c0]);
                bf[ni][1] = __float_as_uint(Bs[(ks + tig + 4) * 136 + c0]);
            }
#pragma unroll
            for (int mi = 0; mi < 4; mi++)
#pragma unroll
                for (int ni = 0; ni < 4; ni++)
                    mma_tf32(acc[mi][ni], af[mi], bf[ni]);
        }
    }

#pragma unroll
    for (int mi = 0; mi < 4; mi++) {
#pragma unroll
        for (int ni = 0; ni < 4; ni++) {
            int row = rowBase + warp_m + mi * 16 + gid;
            int col = colBase + warp_n + ni * 8 + 2 * tig;
            *(float2*)(C + (size_t)row * ldc + col) =
                make_float2(acc[mi][ni][0], acc[mi][ni][1]);
            *(float2*)(C + (size_t)(row + 8) * ldc + col) =
                make_float2(acc[mi][ni][2], acc[mi][ni][3]);
        }
    }
}

// ---------------------------------------------------------------------------
// Fused prep: hh in [0,20) -> RoPE+RMSNorm q/k (packed bf16 hi/lo);
//             hh in [20,24) -> v gate (+ tf32 round). grid = B*S*24, block 64
// ---------------------------------------------------------------------------
__global__ void prep_kernel(const float* __restrict__ cosp,
                            const float* __restrict__ sinp,
                            const float* __restrict__ x,
                            const float* __restrict__ ve,
                            const float* __restrict__ Wg)
{
    int blk = blockIdx.x;
    int hh = blk % (NH + NKV + NKV);
    int bs = blk / (NH + NKV + NKV);
    int d = threadIdx.x;

    if (hh >= NH + NKV) {
        int kvh = hh - (NH + NKV);
        const float* xr = x + (size_t)bs * DD;
        float g = 0.f;
#pragma unroll
        for (int c = 0; c < GATE_CH; c++) g += xr[c] * Wg[c * NKV + kvh];
        g = 3.f / (1.f + __expf(-g));
        float* vp = &g_qkv[(size_t)bs * QKVLD + 1280 + kvh * HD + d];
        *vp = to_tf32(*vp + g * ve[(size_t)bs * (NKV * HD) + kvh * HD + d]);
        return;
    }

    int s = bs % SS;
    const float* ptr = g_qkv + (size_t)bs * QKVLD +
                       ((hh < NH) ? hh * HD : 1024 + (hh - NH) * HD);

    int half = d & 31;
    float c  = cosp[s * 32 + half];
    float sn = sinp[s * 32 + half];
    float x1 = ptr[half];
    float x2 = ptr[half + 32];
    float rot = (d < 32) ? (x1 * c + x2 * sn) : (-x1 * sn + x2 * c);

    __shared__ float red[2];
    float v = rot * rot;
#pragma unroll
    for (int o = 16; o > 0; o >>= 1) v += __shfl_xor_sync(0xffffffffu, v, o);
    if ((d & 31) == 0) red[d >> 5] = v;
    __syncthreads();
    float total = red[0] + red[1];
    float r = rsqrtf(total * (1.f / HD) + EPSV) * 1.2f;
    float val = rot * r;
    if (hh < NH) val *= 0.125f;

    float hif = __bfloat162float(__float2bfloat16(val));
    float lof = val - hif;
    float val_o = __shfl_down_sync(0xffffffffu, val, 1);
    float lof_o = __shfl_down_sync(0xffffffffu, lof, 1);

    if ((d & 1) == 0) {
        uint32_t hp = pack_bf16(val, val_o);
        uint32_t lp = pack_bf16(lof, lof_o);
        uint32_t* out = (hh < NH)
            ? &g_qpk[((size_t)bs * NH + hh) * 64]
            : &g_kpk[((size_t)bs * NKV + (hh - NH)) * 64];
        out[d >> 1]        = hp;
        out[32 + (d >> 1)] = lp;
    }
}

// ---------------------------------------------------------------------------
// Tensor-core flash attention, 128 queries/CTA, 8 warps (R7 structure).
// QK^T: bf16 m16n8k16 hi/lo compensated; PV: tf32 m16n8k8.
// Epilogue writes tf32-rounded output (feeds cp.async Wo GEMM directly).
// ---------------------------------------------------------------------------
#define ATS 68
#define TILEF (64 * ATS)
__global__ __launch_bounds__(256, 2) void attn_tc(const int* __restrict__ winp)
{
    const int win = *winp;
    int bid = blockIdx.x;
    int qt = bid & 15;
    int bh = bid >> 4;
    int h = bh % NH;
    int b = bh / NH;
    int q0 = qt * 128;
    int kvh = h / (NH / NKV);

    const int tid = threadIdx.x;
    const int lane = tid & 31;
    const int warp = tid >> 5;
    const int wrow = warp * 16;
    const int gid = lane >> 2;
    const int tig = lane & 3;

    extern __shared__ float sm[];
    uint32_t* Khl0 = (uint32_t*)sm;
    float* Ss   = sm + 4 * TILEF;
    float* scb  = sm + 4 * TILEF + 128 * ATS;
    float* lbuf = scb + 128;
    uint32_t smbase = (uint32_t)__cvta_generic_to_shared(sm);

    const int st_r  = tid >> 4;
    const int st_c4 = (tid & 15) * 4;

    {
        uint32_t* Qs = (uint32_t*)Ss;
        for (int i = tid; i < 128 * 16; i += 256) {
            int r = i >> 4;
            int c4 = (i & 15) * 4;
            *(uint4*)&Qs[r * ATS + c4] =
                *(const uint4*)(g_qpk + ((size_t)(b * SS + q0 + r) * NH + h) * 64 + c4);
        }
    }
    __syncthreads();

    uint32_t ahi[4][4], alo[4][4];
    {
        const uint32_t* Qs = (const uint32_t*)Ss;
#pragma unroll
        for (int ks = 0; ks < 4; ks++) {
            int cb = ks * 8 + tig;
            ahi[ks][0] = Qs[(wrow + gid) * ATS + cb];
            ahi[ks][1] = Qs[(wrow + gid + 8) * ATS + cb];
            ahi[ks][2] = Qs[(wrow + gid) * ATS + cb + 4];
            ahi[ks][3] = Qs[(wrow + gid + 8) * ATS + cb + 4];
            alo[ks][0] = Qs[(wrow + gid) * ATS + 32 + cb];
            alo[ks][1] = Qs[(wrow + gid + 8) * ATS + 32 + cb];
            alo[ks][2] = Qs[(wrow + gid) * ATS + 32 + cb + 4];
            alo[ks][3] = Qs[(wrow + gid + 8) * ATS + 32 + cb + 4];
        }
    }

    float m = -1e30f, lsum = 0.f;
    float oacc[8][4] = {};

    int kmin = q0 - win + 1;
    if (kmin < 0) kmin = 0;
    int t0 = kmin >> 6;
    int t1 = (q0 + 127) >> 6;

    {
        int kb = t0 << 6;
        const uint32_t* ksrc = g_kpk + ((size_t)(b * SS + kb + st_r) * NKV + kvh) * 64 + st_c4;
        const float* vsrc = g_qkv + (size_t)(b * SS + kb + st_r) * QKVLD + 1280 + kvh * HD + st_c4;
        uint32_t kdst = smbase + (0 * TILEF + st_r * ATS + st_c4) * 4;
        uint32_t vdst = smbase + (2 * TILEF + st_r * ATS + st_c4) * 4;
#pragma unroll
        for (int j = 0; j < 4; j++) {
            cp_async16(kdst + j * 16 * ATS * 4, ksrc + (size_t)j * 16 * NKV * 64);
            cp_async16(vdst + j * 16 * ATS * 4, vsrc + (size_t)j * 16 * QKVLD);
        }
        CP_COMMIT();
    }

    for (int t = t0; t <= t1; t++) {
        int kb = t << 6;
        const int buf = (t - t0) & 1;
        __syncthreads();
        if (t < t1) {
            int nb = (t + 1) << 6;
            const uint32_t* ksrc = g_kpk + ((size_t)(b * SS + nb + st_r) * NKV + kvh) * 64 + st_c4;
            const float* vsrc = g_qkv + (size_t)(b * SS + nb + st_r) * QKVLD + 1280 + kvh * HD + st_c4;
            uint32_t kdst = smbase + ((buf ^ 1) * TILEF + st_r * ATS + st_c4) * 4;
            uint32_t vdst = smbase + ((2 + (buf ^ 1)) * TILEF + st_r * ATS + st_c4) * 4;
#pragma unroll
            for (int j = 0; j < 4; j++) {
                cp_async16(kdst + j * 16 * ATS * 4, ksrc + (size_t)j * 16 * NKV * 64);
                cp_async16(vdst + j * 16 * ATS * 4, vsrc + (size_t)j * 16 * QKVLD);
            }
            CP_COMMIT();
            CP_WAIT(1);
        } else {
            CP_WAIT(0);
        }
        __syncthreads();

        bool active = (kb <= q0 + wrow + 15) && (kb + 63 >= q0 + wrow - win + 1);
        if (active) {
            const uint32_t* Khl = Khl0 + buf * TILEF;
            const float* Vs = sm + (2 + buf) * TILEF;

            float accS[8][4] = {};
#pragma unroll
            for (int ks = 0; ks < 4; ks++) {
#pragma unroll
                for (int ni = 0; ni < 8; ni++) {
                    const uint32_t* kr = &Khl[(ni * 8 + gid) * ATS + ks * 8 + tig];
                    uint32_t bh2[2] = { kr[0],  kr[4] };
                    uint32_t bl2[2] = { kr[32], kr[36] };
                    mma_bf16(accS[ni], ahi[ks], bh2);
                    mma_bf16(accS[ni], alo[ks], bh2);
                    mma_bf16(accS[ni], ahi[ks], bl2);
                }
            }

#pragma unroll
            for (int ni = 0; ni < 8; ni++) {
#pragma unroll
                for (int j = 0; j < 4; j++) {
                    int col = ni * 8 + 2 * tig + (j & 1);
                    int r = gid + ((j >> 1) << 3);
                    int qpos = q0 + wrow + r;
                    int kpos = kb + col;
                    bool ok = (kpos <= qpos) && (kpos >= qpos - win + 1);
                    Ss[(wrow + r) * ATS + col] = ok ? accS[ni][j] : -1e30f;
                }
            }
            __syncwarp();

            {
                int srow = lane >> 1;
                int cb = (lane & 1) * 32;
                float* sp = &Ss[(wrow + srow) * ATS + cb];
                float rmax = -1e30f;
#pragma unroll
                for (int c = 0; c < 32; c++) rmax = fmaxf(rmax, sp[c]);
                rmax = fmaxf(rmax, __shfl_xor_sync(0xffffffffu, rmax, 1));
                float mnew = fmaxf(m, rmax);
                float scale, rs = 0.f;
                if (mnew <= -1e20f) {
                    scale = 1.f;
#pragma unroll
                    for (int c = 0; c < 32; c++) sp[c] = 0.f;
                } else {
                    scale = __expf(m - mnew);
#pragma unroll
                    for (int c = 0; c < 32; c++) {
                        float p = __expf(sp[c] - mnew);
                        rs += p;
                        sp[c] = to_tf32(p);
                    }
                }
                m = mnew;
                rs += __shfl_xor_sync(0xffffffffu, rs, 1);
                lsum = lsum * scale + rs;
                if ((lane & 1) == 0) scb[wrow + srow] = scale;
            }
            __syncwarp();

            {
                float sc0 = scb[wrow + gid];
                float sc1 = scb[wrow + gid + 8];
#pragma unroll
                for (int ni = 0; ni < 8; ni++) {
                    oacc[ni][0] *= sc0; oacc[ni][1] *= sc0;
                    oacc[ni][2] *= sc1; oacc[ni][3] *= sc1;
                }
            }
#pragma unroll
            for (int ks = 0; ks < 8; ks++) {
                uint32_t pa[4];
                pa[0] = __float_as_uint(Ss[(wrow + gid) * ATS + ks * 8 + tig]);
                pa[1] = __float_as_uint(Ss[(wrow + gid + 8) * ATS + ks * 8 + tig]);
                pa[2] = __float_as_uint(Ss[(wrow + gid) * ATS + ks * 8 + tig + 4]);
                pa[3] = __float_as_uint(Ss[(wrow + gid + 8) * ATS + ks * 8 + tig + 4]);
#pragma unroll
                for (int ni = 0; ni < 8; ni++) {
                    uint32_t vb[2];
                    vb[0] = __float_as_uint(Vs[(ks * 8 + tig) * ATS + ni * 8 + gid]);
                    vb[1] = __float_as_uint(Vs[(ks * 8 + tig + 4) * ATS + ni * 8 + gid]);
                    mma_tf32(oacc[ni], pa, vb);
                }
            }
        }
    }

    // ---- normalize and write out (tf32-rounded for the cp.async Wo GEMM) ----
    if ((lane & 1) == 0) lbuf[wrow + (lane >> 1)] = lsum;
    __syncwarp();
    float li0 = 1.f / lbuf[wrow + gid];
    float li1 = 1.f / lbuf[wrow + gid + 8];

#pragma unroll
    for (int ni = 0; ni < 8; ni++) {
        int col = h * HD + ni * 8 + 2 * tig;
        int row0 = b * SS + q0 + wrow + gid;
        *(float2*)(g_y + (size_t)row0 * DD + col) =
            make_float2(to_tf32(oacc[ni][0] * li0), to_tf32(oacc[ni][1] * li0));
        *(float2*)(g_y + (size_t)(row0 + 8) * DD + col) =
            make_float2(to_tf32(oacc[ni][2] * li1), to_tf32(oacc[ni][3] * li1));
    }
}

// ---------------------------------------------------------------------------
extern "C" void kernel_launch(void* const* d_in, const int* in_sizes, int n_in,
                              void* d_out, int out_size)
{
    const float* x    = (const float*)d_in[0];
    const float* ve   = (const float*)d_in[1];
    const float* cosp = (const float*)d_in[2];
    const float* sinp = (const float*)d_in[3];
    const float* Wq   = (const float*)d_in[4];
    const float* Wk   = (const float*)d_in[5];
    const float* Wv   = (const float*)d_in[6];
    const float* Wo   = (const float*)d_in[7];
    const float* Wg   = (const float*)d_in[8];
    const int*   win  = (const int*)d_in[9];
    float* out = (float*)d_out;

    float *pqkv, *py, *pxr, *pwqkv, *pwo;
    cudaGetSymbolAddress((void**)&pqkv, g_qkv);
    cudaGetSymbolAddress((void**)&py, g_y);
    cudaGetSymbolAddress((void**)&pxr, g_xr);
    cudaGetSymbolAddress((void**)&pwqkv, g_wqkv);
    cudaGetSymbolAddress((void**)&pwo, g_wo);

    const int M = BB * SS;   // 4096

    // tf32 pre-rounding (operands become raw-copyable by cp.async)
    round_x<<<M, 256>>>(x);
    round_w<<<1024, 256>>>(Wq, pwqkv, 1024, QKVLD, 0);
    round_w<<<256, 256>>>(Wk, pwqkv, 256, QKVLD, 1024);
    round_w<<<256, 256>>>(Wv, pwqkv, 256, QKVLD, 1280);
    round_w<<<1024, 256>>>(Wo, pwo, 1024, DD, 0);

    cudaFuncSetAttribute(gemm_ca, cudaFuncAttributeMaxDynamicSharedMemorySize, GCA_SMEM);

    // fused QKV projection (tf32 HMMA, 3-stage cp.async)
    gemm_ca<<<dim3(QKVLD / 128, M / 128), 256, GCA_SMEM>>>(pxr, pwqkv, pqkv, DD, QKVLD, QKVLD);

    // fused v-gate + RoPE/RMSNorm + bf16 hi/lo packing
    prep_kernel<<<M * (NH + 2 * NKV), HD>>>(cosp, sinp, x, ve, Wg);

    // flash attention
    {
        int smem = (4 * TILEF + 128 * ATS + 256) * sizeof(float);   // 105472 B
        cudaFuncSetAttribute(attn_tc, cudaFuncAttributeMaxDynamicSharedMemorySize, smem);
        attn_tc<<<BB * NH * (SS / 128), 256, smem>>>(win);
    }

    // output projection (tf32 HMMA, 3-stage cp.async)
    gemm_ca<<<dim3(DD / 128, M / 128), 256, GCA_SMEM>>>(py, pwo, out, DD, DD, DD);
}